// round 15
// baseline (speedup 1.0000x reference)
#include <cuda_runtime.h>
#include <cstdint>

#define NN 50000
#define EE 800000
#define F1 256      // layer1 hidden (H*C = 8*32)
#define H1 8
#define F2 64       // layer2 output
#define SCAN_B 196  // ceil(50000/256)

// ---------------- static scratch ----------
__device__ float g_xlr1[(size_t)NN * 512];   // [n][0:256)=xl1, [256:512)=xr1
__device__ float g_h1[NN * F1];              // relu(aggr/den + b1)
__device__ float g_xlr2[(size_t)NN * 128];   // [n][0:64)=xl2, [64:128)=xr2

__device__ float g_Bp1[256 * 512];           // Wl1 | Wr1
__device__ float g_Bp2[256 * 128];           // Wl2 | Wr2

// sort scratch (CSR: start(n) = g_pos[n] - g_cnt[n], end(n) = g_pos[n])
__device__ int g_cnt[NN];
__device__ int g_bsum[SCAN_B];
__device__ int g_pos[NN];
__device__ int g_perm[EE];                   // src ids, sorted by dst

__device__ __forceinline__ uint32_t to_tf32(float f) {
    uint32_t o;
    asm("cvt.rna.tf32.f32 %0, %1;" : "=r"(o) : "f"(f));
    return o;
}
__device__ __forceinline__ void cp_async16(uint32_t smem_dst, const void* gmem_src, int src_bytes) {
    asm volatile("cp.async.cg.shared.global [%0], [%1], 16, %2;"
                 :: "r"(smem_dst), "l"(gmem_src), "r"(src_bytes));
}
__device__ __forceinline__ void cp_commit() {
    asm volatile("cp.async.commit_group;");
}
template <int N>
__device__ __forceinline__ void cp_wait() {
    asm volatile("cp.async.wait_group %0;" :: "n"(N));
}

// ---------------- init (only histogram counters) ----------------------------
__global__ void init_kernel() {
    int i = blockIdx.x * blockDim.x + threadIdx.x;
    if (i < NN) g_cnt[i] = 0;
}

// ---------------- weight packing: Bp = [Wl | Wr] ----------------------------
__global__ void pack_kernel(const float* __restrict__ Wl, const float* __restrict__ Wr,
                            float* __restrict__ Bp, int K, int Mh) {
    int i = blockIdx.x * blockDim.x + threadIdx.x;
    if (i >= K * Mh) return;
    int k = i / Mh, j = i % Mh;
    Bp[(size_t)k * 2 * Mh + j]      = Wl[i];
    Bp[(size_t)k * 2 * Mh + Mh + j] = Wr[i];
}

// ---------------- counting sort by dst --------------------------------------
__global__ void hist_kernel(const int* __restrict__ ei, int E) {
    int i = blockIdx.x * blockDim.x + threadIdx.x;
    int stride = gridDim.x * blockDim.x;
    for (int e = i; e < E; e += stride)
        atomicAdd(&g_cnt[ei[E + e]], 1);
}

__global__ void scanA_kernel() {
    __shared__ int sh[256];
    int b = blockIdx.x, t = threadIdx.x;
    int i = b * 256 + t;
    int v = (i < NN) ? g_cnt[i] : 0;
    sh[t] = v; __syncthreads();
    for (int off = 128; off; off >>= 1) {
        if (t < off) sh[t] += sh[t + off];
        __syncthreads();
    }
    if (t == 0) g_bsum[b] = sh[0];
}

__global__ void scanB_kernel() {
    __shared__ int sh[256];
    int t = threadIdx.x;
    int v = (t < SCAN_B) ? g_bsum[t] : 0;
    sh[t] = v; __syncthreads();
#pragma unroll
    for (int off = 1; off < 256; off <<= 1) {
        int x = (t >= off) ? sh[t - off] : 0;
        __syncthreads();
        sh[t] += x;
        __syncthreads();
    }
    if (t < SCAN_B) g_bsum[t] = sh[t] - v;
}

__global__ void scanC_kernel() {
    __shared__ int sh[256];
    int b = blockIdx.x, t = threadIdx.x;
    int i = b * 256 + t;
    int v = (i < NN) ? g_cnt[i] : 0;
    sh[t] = v; __syncthreads();
#pragma unroll
    for (int off = 1; off < 256; off <<= 1) {
        int x = (t >= off) ? sh[t - off] : 0;
        __syncthreads();
        sh[t] += x;
        __syncthreads();
    }
    if (i < NN) g_pos[i] = g_bsum[b] + sh[t] - v;
}

__global__ void scatter_kernel(const int* __restrict__ ei, int E) {
    int i = blockIdx.x * blockDim.x + threadIdx.x;
    int stride = gridDim.x * blockDim.x;
    for (int e = i; e < E; e += stride) {
        int s = ei[e], d = ei[E + e];
        int pos = atomicAdd(&g_pos[d], 1);
        g_perm[pos] = s;
    }
}

// ---------------- TF32 tensor GEMM, cp.async double-buffered ----------------
// C[N,M] = A[N,K] @ B[K,M]. Block 128x128, BK=16, 8 warps (2x4),
// warp tile 64x32, fp32 accumulate. Single __syncthreads per k-step:
// wait(tile i) -> sync -> prefetch(tile i+1, overwrites buffer of i-1 which
// every thread finished before reaching this sync) -> compute(tile i).
__global__ __launch_bounds__(256) void tf32_gemm(
        const float* __restrict__ A, const float* __restrict__ B,
        float* __restrict__ C, int N, int K, int M) {
    __shared__ float As[2][128][20];
    __shared__ float Bs[2][16][132];

    int tid = threadIdx.x;
    int lane = tid & 31;
    int wid = tid >> 5;
    int wm = wid >> 2;
    int wn = wid & 3;
    int rowBase = blockIdx.y * 128;
    int colBase = blockIdx.x * 128;

    uint32_t sA = (uint32_t)__cvta_generic_to_shared(&As[0][0][0]);
    uint32_t sB = (uint32_t)__cvta_generic_to_shared(&Bs[0][0][0]);

    int ar = tid >> 2;
    int akk = (tid & 3) * 4;
    int bkk = tid >> 5;
    int bcc = (tid & 31) * 4;

    auto loadTiles = [&](int buf, int k0) {
#pragma unroll
        for (int i = 0; i < 2; i++) {
            int r = ar + 64 * i;
            int grow = rowBase + r;
            const float* src = A + (size_t)grow * K + k0 + akk;
            uint32_t dst = sA + (uint32_t)(((buf * 128 + r) * 20 + akk) * 4);
            cp_async16(dst, src, grow < N ? 16 : 0);
        }
#pragma unroll
        for (int i = 0; i < 2; i++) {
            int kk = bkk + 8 * i;
            const float* src = B + (size_t)(k0 + kk) * M + colBase + bcc;
            uint32_t dst = sB + (uint32_t)(((buf * 16 + kk) * 132 + bcc) * 4);
            cp_async16(dst, src, 16);
        }
        cp_commit();
    };

    float c[16][4] = {};
    int l4 = lane >> 2;
    int l3 = lane & 3;

    loadTiles(0, 0);

    for (int k0 = 0; k0 < K; k0 += 16) {
        int buf = (k0 >> 4) & 1;
        cp_wait<0>();            // tile for `buf` resident
        __syncthreads();         // visibility + prev-tile compute completion
        if (k0 + 16 < K) loadTiles(buf ^ 1, k0 + 16);

#pragma unroll
        for (int ks = 0; ks < 2; ks++) {
            int kb = ks * 8;
            uint32_t af[4][4];
#pragma unroll
            for (int mi = 0; mi < 4; mi++) {
                int r = wm * 64 + mi * 16 + l4;
                af[mi][0] = to_tf32(As[buf][r][kb + l3]);
                af[mi][1] = to_tf32(As[buf][r + 8][kb + l3]);
                af[mi][2] = to_tf32(As[buf][r][kb + l3 + 4]);
                af[mi][3] = to_tf32(As[buf][r + 8][kb + l3 + 4]);
            }
            uint32_t bf[4][2];
#pragma unroll
            for (int ni = 0; ni < 4; ni++) {
                int ccol = wn * 32 + ni * 8 + l4;
                bf[ni][0] = to_tf32(Bs[buf][kb + l3][ccol]);
                bf[ni][1] = to_tf32(Bs[buf][kb + l3 + 4][ccol]);
            }
#pragma unroll
            for (int mi = 0; mi < 4; mi++)
#pragma unroll
                for (int ni = 0; ni < 4; ni++) {
                    float* cr = c[mi * 4 + ni];
                    asm volatile(
                        "mma.sync.aligned.m16n8k8.row.col.f32.tf32.tf32.f32 "
                        "{%0,%1,%2,%3}, {%4,%5,%6,%7}, {%8,%9}, {%0,%1,%2,%3};"
                        : "+f"(cr[0]), "+f"(cr[1]), "+f"(cr[2]), "+f"(cr[3])
                        : "r"(af[mi][0]), "r"(af[mi][1]), "r"(af[mi][2]), "r"(af[mi][3]),
                          "r"(bf[ni][0]), "r"(bf[ni][1]));
                }
        }
    }

#pragma unroll
    for (int mi = 0; mi < 4; mi++) {
        int r0 = rowBase + wm * 64 + mi * 16 + l4;
#pragma unroll
        for (int ni = 0; ni < 4; ni++) {
            int cc = colBase + wn * 32 + ni * 8 + l3 * 2;
            float* cr = c[mi * 4 + ni];
            if (r0 < N)
                *(float2*)(C + (size_t)r0 * M + cc) = make_float2(cr[0], cr[1]);
            if (r0 + 8 < N)
                *(float2*)(C + (size_t)(r0 + 8) * M + cc) = make_float2(cr[2], cr[3]);
        }
    }
}

// ---------------- layer-1: 2 warps per node, 2-edge unrolled ----------------
// Warp w of node n owns channels [w*128,(w+1)*128) = heads [w*4,(w+1)*4).
// Heads never straddle warps: no cross-warp reduction, no atomics.
__global__ void agg_node1(const float* __restrict__ att,
                          const float* __restrict__ b1) {
    int gw = (int)((blockIdx.x * blockDim.x + threadIdx.x) >> 5);
    int n = gw >> 1;
    int w = gw & 1;
    int lane = threadIdx.x & 31;
    if (n >= NN) return;

    int end = g_pos[n];
    int start = end - g_cnt[n];
    int fi = w * 32 + lane;          // float4 index within the node row (0..63)

    float4 t = ((const float4*)att)[fi];
    float4 b = ((const float4*)(g_xlr1 + (size_t)n * 512 + 256))[fi];

    float4 acc = make_float4(0, 0, 0, 0);
    float dn = 0.f;

    int e = start;
    for (; e + 1 < end; e += 2) {
        int s0 = g_perm[e];
        int s1 = g_perm[e + 1];
        float4 a0 = ((const float4*)(g_xlr1 + (size_t)s0 * 512))[fi];
        float4 a1 = ((const float4*)(g_xlr1 + (size_t)s1 * 512))[fi];

        float v, p0 = 0.f, p1 = 0.f;
        v = a0.x + b.x; p0 += (v > 0.f ? v : 0.2f * v) * t.x;
        v = a0.y + b.y; p0 += (v > 0.f ? v : 0.2f * v) * t.y;
        v = a0.z + b.z; p0 += (v > 0.f ? v : 0.2f * v) * t.z;
        v = a0.w + b.w; p0 += (v > 0.f ? v : 0.2f * v) * t.w;
        v = a1.x + b.x; p1 += (v > 0.f ? v : 0.2f * v) * t.x;
        v = a1.y + b.y; p1 += (v > 0.f ? v : 0.2f * v) * t.y;
        v = a1.z + b.z; p1 += (v > 0.f ? v : 0.2f * v) * t.z;
        v = a1.w + b.w; p1 += (v > 0.f ? v : 0.2f * v) * t.w;

        // reduce over the 8 lanes of this head (one head = 8 float4 lanes)
#pragma unroll
        for (int o = 1; o < 8; o <<= 1) {
            p0 += __shfl_xor_sync(0xFFFFFFFFu, p0, o);
            p1 += __shfl_xor_sync(0xFFFFFFFFu, p1, o);
        }
        float e0 = __expf(p0), e1 = __expf(p1);

        acc.x += a0.x * e0 + a1.x * e1;
        acc.y += a0.y * e0 + a1.y * e1;
        acc.z += a0.z * e0 + a1.z * e1;
        acc.w += a0.w * e0 + a1.w * e1;
        dn += e0 + e1;
    }
    if (e < end) {
        int s = g_perm[e];
        float4 a = ((const float4*)(g_xlr1 + (size_t)s * 512))[fi];
        float v, p = 0.f;
        v = a.x + b.x; p += (v > 0.f ? v : 0.2f * v) * t.x;
        v = a.y + b.y; p += (v > 0.f ? v : 0.2f * v) * t.y;
        v = a.z + b.z; p += (v > 0.f ? v : 0.2f * v) * t.z;
        v = a.w + b.w; p += (v > 0.f ? v : 0.2f * v) * t.w;
#pragma unroll
        for (int o = 1; o < 8; o <<= 1) p += __shfl_xor_sync(0xFFFFFFFFu, p, o);
        float ex = __expf(p);
        acc.x += a.x * ex; acc.y += a.y * ex; acc.z += a.z * ex; acc.w += a.w * ex;
        dn += ex;
    }

    float inv = 1.f / (dn + 1e-16f);
    float4 bb = ((const float4*)b1)[fi];
    float4 r;
    r.x = fmaxf(acc.x * inv + bb.x, 0.f);
    r.y = fmaxf(acc.y * inv + bb.y, 0.f);
    r.z = fmaxf(acc.z * inv + bb.z, 0.f);
    r.w = fmaxf(acc.w * inv + bb.w, 0.f);
    ((float4*)(g_h1 + (size_t)n * F1))[fi] = r;
}

// ---------------- layer-2: half-warp per node, 4-edge unrolled --------------
__global__ void agg_node2(const float* __restrict__ att,
                          const float* __restrict__ b2,
                          float* __restrict__ out) {
    int n = (int)((blockIdx.x * blockDim.x + threadIdx.x) >> 4);
    int l16 = threadIdx.x & 15;
    unsigned hm = 0xFFFFu << (threadIdx.x & 16);
    if (n >= NN) return;

    int end = g_pos[n];
    int start = end - g_cnt[n];

    float4 t = ((const float4*)att)[l16];
    float4 b = ((const float4*)(g_xlr2 + (size_t)n * 128 + 64))[l16];

    float4 acc = make_float4(0, 0, 0, 0);
    float dn = 0.f;

    int e = start;
    for (; e + 3 < end; e += 4) {
        int s0 = g_perm[e], s1 = g_perm[e + 1], s2 = g_perm[e + 2], s3 = g_perm[e + 3];
        float4 a0 = ((const float4*)(g_xlr2 + (size_t)s0 * 128))[l16];
        float4 a1 = ((const float4*)(g_xlr2 + (size_t)s1 * 128))[l16];
        float4 a2 = ((const float4*)(g_xlr2 + (size_t)s2 * 128))[l16];
        float4 a3 = ((const float4*)(g_xlr2 + (size_t)s3 * 128))[l16];

        float v, p0 = 0.f, p1 = 0.f, p2 = 0.f, p3 = 0.f;
        v = a0.x + b.x; p0 += (v > 0.f ? v : 0.2f * v) * t.x;
        v = a0.y + b.y; p0 += (v > 0.f ? v : 0.2f * v) * t.y;
        v = a0.z + b.z; p0 += (v > 0.f ? v : 0.2f * v) * t.z;
        v = a0.w + b.w; p0 += (v > 0.f ? v : 0.2f * v) * t.w;
        v = a1.x + b.x; p1 += (v > 0.f ? v : 0.2f * v) * t.x;
        v = a1.y + b.y; p1 += (v > 0.f ? v : 0.2f * v) * t.y;
        v = a1.z + b.z; p1 += (v > 0.f ? v : 0.2f * v) * t.z;
        v = a1.w + b.w; p1 += (v > 0.f ? v : 0.2f * v) * t.w;
        v = a2.x + b.x; p2 += (v > 0.f ? v : 0.2f * v) * t.x;
        v = a2.y + b.y; p2 += (v > 0.f ? v : 0.2f * v) * t.y;
        v = a2.z + b.z; p2 += (v > 0.f ? v : 0.2f * v) * t.z;
        v = a2.w + b.w; p2 += (v > 0.f ? v : 0.2f * v) * t.w;
        v = a3.x + b.x; p3 += (v > 0.f ? v : 0.2f * v) * t.x;
        v = a3.y + b.y; p3 += (v > 0.f ? v : 0.2f * v) * t.y;
        v = a3.z + b.z; p3 += (v > 0.f ? v : 0.2f * v) * t.z;
        v = a3.w + b.w; p3 += (v > 0.f ? v : 0.2f * v) * t.w;

#pragma unroll
        for (int o = 1; o < 16; o <<= 1) {
            p0 += __shfl_xor_sync(hm, p0, o);
            p1 += __shfl_xor_sync(hm, p1, o);
            p2 += __shfl_xor_sync(hm, p2, o);
            p3 += __shfl_xor_sync(hm, p3, o);
        }
        float e0 = __expf(p0), e1 = __expf(p1), e2 = __expf(p2), e3 = __expf(p3);

        acc.x += a0.x * e0 + a1.x * e1 + a2.x * e2 + a3.x * e3;
        acc.y += a0.y * e0 + a1.y * e1 + a2.y * e2 + a3.y * e3;
        acc.z += a0.z * e0 + a1.z * e1 + a2.z * e2 + a3.z * e3;
        acc.w += a0.w * e0 + a1.w * e1 + a2.w * e2 + a3.w * e3;
        dn += e0 + e1 + e2 + e3;
    }
    for (; e < end; e++) {
        int s = g_perm[e];
        float4 a = ((const float4*)(g_xlr2 + (size_t)s * 128))[l16];
        float v, p = 0.f;
        v = a.x + b.x; p += (v > 0.f ? v : 0.2f * v) * t.x;
        v = a.y + b.y; p += (v > 0.f ? v : 0.2f * v) * t.y;
        v = a.z + b.z; p += (v > 0.f ? v : 0.2f * v) * t.z;
        v = a.w + b.w; p += (v > 0.f ? v : 0.2f * v) * t.w;
#pragma unroll
        for (int o = 1; o < 16; o <<= 1) p += __shfl_xor_sync(hm, p, o);
        float ex = __expf(p);
        acc.x += a.x * ex; acc.y += a.y * ex; acc.z += a.z * ex; acc.w += a.w * ex;
        dn += ex;
    }

    float inv = 1.f / (dn + 1e-16f);
    float4 bb = ((const float4*)b2)[l16];
    float4 vv;
    vv.x = acc.x * inv + bb.x;
    vv.y = acc.y * inv + bb.y;
    vv.z = acc.z * inv + bb.z;
    vv.w = acc.w * inv + bb.w;

    float mx = fmaxf(fmaxf(vv.x, vv.y), fmaxf(vv.z, vv.w));
#pragma unroll
    for (int o = 1; o < 16; o <<= 1) mx = fmaxf(mx, __shfl_xor_sync(hm, mx, o));
    float se = __expf(vv.x - mx) + __expf(vv.y - mx) + __expf(vv.z - mx) + __expf(vv.w - mx);
#pragma unroll
    for (int o = 1; o < 16; o <<= 1) se += __shfl_xor_sync(hm, se, o);
    float lse = mx + __logf(se);

    ((float4*)(out + (size_t)n * F2))[l16] = vv;
    float4 ls;
    ls.x = vv.x - lse; ls.y = vv.y - lse; ls.z = vv.z - lse; ls.w = vv.w - lse;
    ((float4*)(out + (size_t)NN * F2 + (size_t)n * F2))[l16] = ls;
}

// ---------------- launch ----------------------------------------------------
extern "C" void kernel_launch(void* const* d_in, const int* in_sizes, int n_in,
                              void* d_out, int out_size) {
    const float* x    = (const float*)d_in[0];
    const int*   ei   = (const int*)d_in[1];     // JAX canonicalizes int64 -> int32
    const float* Wl1  = (const float*)d_in[2];
    const float* Wr1  = (const float*)d_in[3];
    const float* att1 = (const float*)d_in[4];
    const float* b1   = (const float*)d_in[5];
    const float* Wl2  = (const float*)d_in[6];
    const float* Wr2  = (const float*)d_in[7];
    const float* att2 = (const float*)d_in[8];
    const float* b2   = (const float*)d_in[9];
    float* out = (float*)d_out;

    int E = in_sizes[1] / 2;
    if (E > EE) E = EE;
    int N = in_sizes[0] / F1;
    if (N > NN) N = NN;

    void *xlr1p, *xlr2p, *h1p, *bp1p, *bp2p;
    cudaGetSymbolAddress(&xlr1p, g_xlr1);
    cudaGetSymbolAddress(&xlr2p, g_xlr2);
    cudaGetSymbolAddress(&h1p,  g_h1);
    cudaGetSymbolAddress(&bp1p, g_Bp1);
    cudaGetSymbolAddress(&bp2p, g_Bp2);

    static cudaStream_t sA = nullptr, sB = nullptr;
    static cudaEvent_t ev0 = nullptr, evS = nullptr, evG = nullptr;
    if (!sA) {
        cudaStreamCreateWithFlags(&sA, cudaStreamNonBlocking);
        cudaStreamCreateWithFlags(&sB, cudaStreamNonBlocking);
        cudaEventCreateWithFlags(&ev0, cudaEventDisableTiming);
        cudaEventCreateWithFlags(&evS, cudaEventDisableTiming);
        cudaEventCreateWithFlags(&evG, cudaEventDisableTiming);
    }

    // fork
    cudaEventRecord(ev0, 0);
    cudaStreamWaitEvent(sA, ev0, 0);
    cudaStreamWaitEvent(sB, ev0, 0);

    // stream A: CSR build (counting sort by dst)
    init_kernel<<<(NN + 255) / 256, 256, 0, sA>>>();
    hist_kernel<<<1024, 256, 0, sA>>>(ei, E);
    scanA_kernel<<<SCAN_B, 256, 0, sA>>>();
    scanB_kernel<<<1, 256, 0, sA>>>();
    scanC_kernel<<<SCAN_B, 256, 0, sA>>>();
    scatter_kernel<<<1024, 256, 0, sA>>>(ei, E);
    cudaEventRecord(evS, sA);

    // stream B: weight packing + layer-1 projection [N,256]@[256,512]
    pack_kernel<<<(256 * 256 + 255) / 256, 256, 0, sB>>>(Wl1, Wr1, (float*)bp1p, 256, 256);
    pack_kernel<<<(256 * 64 + 255) / 256, 256, 0, sB>>>(Wl2, Wr2, (float*)bp2p, 256, 64);
    dim3 grid1(512 / 128, (N + 127) / 128);
    tf32_gemm<<<grid1, 256, 0, sB>>>(x, (const float*)bp1p, (float*)xlr1p, N, F1, 512);
    cudaEventRecord(evG, sB);

    // join
    cudaStreamWaitEvent(0, evS, 0);
    cudaStreamWaitEvent(0, evG, 0);

    // layer-1 aggregation: 2 warps per node
    agg_node1<<<(2 * NN + 7) / 8, 256>>>(att1, b1);

    // layer-2 projection: [N,256]@[256,128] on h1 -> xlr2
    dim3 grid2(1, (N + 127) / 128);
    tf32_gemm<<<grid2, 256>>>((const float*)h1p, (const float*)bp2p, (float*)xlr2p, N, F1, 128);

    // layer-2 aggregation + bias + log_softmax -> out
    agg_node2<<<(NN + 15) / 16, 256>>>(att2, b2, out);

    (void)n_in; (void)out_size;
}

// round 16
// speedup vs baseline: 1.0107x; 1.0107x over previous
#include <cuda_runtime.h>
#include <cstdint>

#define NN 50000
#define EE 800000
#define F1 256      // layer1 hidden (H*C = 8*32)
#define H1 8
#define F2 64       // layer2 output
#define SCAN_B 196  // ceil(50000/256)

// ---------------- static scratch ----------
__device__ float g_xlr1[(size_t)NN * 512];   // [n][0:256)=xl1, [256:512)=xr1
__device__ float g_h1[NN * F1];              // relu(aggr/den + b1)
__device__ float g_xlr2[(size_t)NN * 128];   // [n][0:64)=xl2, [64:128)=xr2

__device__ float g_Bp1[256 * 512];           // Wl1 | Wr1
__device__ float g_Bp2[256 * 128];           // Wl2 | Wr2

// sort scratch (CSR: start(n) = g_pos[n] - g_cnt[n], end(n) = g_pos[n])
__device__ int g_cnt[NN];
__device__ int g_bsum[SCAN_B];
__device__ int g_pos[NN];
__device__ int g_perm[EE];                   // src ids, sorted by dst

__device__ __forceinline__ uint32_t to_tf32(float f) {
    uint32_t o;
    asm("cvt.rna.tf32.f32 %0, %1;" : "=r"(o) : "f"(f));
    return o;
}
__device__ __forceinline__ void cp_async16(uint32_t smem_dst, const void* gmem_src, int src_bytes) {
    asm volatile("cp.async.cg.shared.global [%0], [%1], 16, %2;"
                 :: "r"(smem_dst), "l"(gmem_src), "r"(src_bytes));
}
__device__ __forceinline__ void cp_commit() {
    asm volatile("cp.async.commit_group;");
}
template <int N>
__device__ __forceinline__ void cp_wait() {
    asm volatile("cp.async.wait_group %0;" :: "n"(N));
}

// ---------------- init (only histogram counters) ----------------------------
__global__ void init_kernel() {
    int i = blockIdx.x * blockDim.x + threadIdx.x;
    if (i < NN) g_cnt[i] = 0;
}

// ---------------- weight packing: Bp = [Wl | Wr] ----------------------------
__global__ void pack_kernel(const float* __restrict__ Wl, const float* __restrict__ Wr,
                            float* __restrict__ Bp, int K, int Mh) {
    int i = blockIdx.x * blockDim.x + threadIdx.x;
    if (i >= K * Mh) return;
    int k = i / Mh, j = i % Mh;
    Bp[(size_t)k * 2 * Mh + j]      = Wl[i];
    Bp[(size_t)k * 2 * Mh + Mh + j] = Wr[i];
}

// ---------------- counting sort by dst --------------------------------------
__global__ void hist_kernel(const int* __restrict__ ei, int E) {
    int i = blockIdx.x * blockDim.x + threadIdx.x;
    int stride = gridDim.x * blockDim.x;
    for (int e = i; e < E; e += stride)
        atomicAdd(&g_cnt[ei[E + e]], 1);
}

__global__ void scanA_kernel() {
    __shared__ int sh[256];
    int b = blockIdx.x, t = threadIdx.x;
    int i = b * 256 + t;
    int v = (i < NN) ? g_cnt[i] : 0;
    sh[t] = v; __syncthreads();
    for (int off = 128; off; off >>= 1) {
        if (t < off) sh[t] += sh[t + off];
        __syncthreads();
    }
    if (t == 0) g_bsum[b] = sh[0];
}

__global__ void scanB_kernel() {
    __shared__ int sh[256];
    int t = threadIdx.x;
    int v = (t < SCAN_B) ? g_bsum[t] : 0;
    sh[t] = v; __syncthreads();
#pragma unroll
    for (int off = 1; off < 256; off <<= 1) {
        int x = (t >= off) ? sh[t - off] : 0;
        __syncthreads();
        sh[t] += x;
        __syncthreads();
    }
    if (t < SCAN_B) g_bsum[t] = sh[t] - v;
}

__global__ void scanC_kernel() {
    __shared__ int sh[256];
    int b = blockIdx.x, t = threadIdx.x;
    int i = b * 256 + t;
    int v = (i < NN) ? g_cnt[i] : 0;
    sh[t] = v; __syncthreads();
#pragma unroll
    for (int off = 1; off < 256; off <<= 1) {
        int x = (t >= off) ? sh[t - off] : 0;
        __syncthreads();
        sh[t] += x;
        __syncthreads();
    }
    if (i < NN) g_pos[i] = g_bsum[b] + sh[t] - v;
}

__global__ void scatter_kernel(const int* __restrict__ ei, int E) {
    int i = blockIdx.x * blockDim.x + threadIdx.x;
    int stride = gridDim.x * blockDim.x;
    for (int e = i; e < E; e += stride) {
        int s = ei[e], d = ei[E + e];
        int pos = atomicAdd(&g_pos[d], 1);
        g_perm[pos] = s;
    }
}

// ---------------- TF32 tensor GEMM, cp.async double-buffered (R13) ----------
__global__ __launch_bounds__(256) void tf32_gemm(
        const float* __restrict__ A, const float* __restrict__ B,
        float* __restrict__ C, int N, int K, int M) {
    __shared__ float As[2][128][20];
    __shared__ float Bs[2][16][132];

    int tid = threadIdx.x;
    int lane = tid & 31;
    int wid = tid >> 5;
    int wm = wid >> 2;
    int wn = wid & 3;
    int rowBase = blockIdx.y * 128;
    int colBase = blockIdx.x * 128;

    uint32_t sA = (uint32_t)__cvta_generic_to_shared(&As[0][0][0]);
    uint32_t sB = (uint32_t)__cvta_generic_to_shared(&Bs[0][0][0]);

    int ar = tid >> 2;
    int akk = (tid & 3) * 4;
    int bkk = tid >> 5;
    int bcc = (tid & 31) * 4;

    auto loadTiles = [&](int buf, int k0) {
#pragma unroll
        for (int i = 0; i < 2; i++) {
            int r = ar + 64 * i;
            int grow = rowBase + r;
            const float* src = A + (size_t)grow * K + k0 + akk;
            uint32_t dst = sA + (uint32_t)(((buf * 128 + r) * 20 + akk) * 4);
            cp_async16(dst, src, grow < N ? 16 : 0);
        }
#pragma unroll
        for (int i = 0; i < 2; i++) {
            int kk = bkk + 8 * i;
            const float* src = B + (size_t)(k0 + kk) * M + colBase + bcc;
            uint32_t dst = sB + (uint32_t)(((buf * 16 + kk) * 132 + bcc) * 4);
            cp_async16(dst, src, 16);
        }
        cp_commit();
    };

    float c[16][4] = {};
    int l4 = lane >> 2;
    int l3 = lane & 3;

    loadTiles(0, 0);

    for (int k0 = 0; k0 < K; k0 += 16) {
        int buf = (k0 >> 4) & 1;
        bool more = (k0 + 16) < K;
        if (more) loadTiles(buf ^ 1, k0 + 16);
        if (more) cp_wait<1>(); else cp_wait<0>();
        __syncthreads();

#pragma unroll
        for (int ks = 0; ks < 2; ks++) {
            int kb = ks * 8;
            uint32_t af[4][4];
#pragma unroll
            for (int mi = 0; mi < 4; mi++) {
                int r = wm * 64 + mi * 16 + l4;
                af[mi][0] = to_tf32(As[buf][r][kb + l3]);
                af[mi][1] = to_tf32(As[buf][r + 8][kb + l3]);
                af[mi][2] = to_tf32(As[buf][r][kb + l3 + 4]);
                af[mi][3] = to_tf32(As[buf][r + 8][kb + l3 + 4]);
            }
            uint32_t bf[4][2];
#pragma unroll
            for (int ni = 0; ni < 4; ni++) {
                int ccol = wn * 32 + ni * 8 + l4;
                bf[ni][0] = to_tf32(Bs[buf][kb + l3][ccol]);
                bf[ni][1] = to_tf32(Bs[buf][kb + l3 + 4][ccol]);
            }
#pragma unroll
            for (int mi = 0; mi < 4; mi++)
#pragma unroll
                for (int ni = 0; ni < 4; ni++) {
                    float* cr = c[mi * 4 + ni];
                    asm volatile(
                        "mma.sync.aligned.m16n8k8.row.col.f32.tf32.tf32.f32 "
                        "{%0,%1,%2,%3}, {%4,%5,%6,%7}, {%8,%9}, {%0,%1,%2,%3};"
                        : "+f"(cr[0]), "+f"(cr[1]), "+f"(cr[2]), "+f"(cr[3])
                        : "r"(af[mi][0]), "r"(af[mi][1]), "r"(af[mi][2]), "r"(af[mi][3]),
                          "r"(bf[ni][0]), "r"(bf[ni][1]));
                }
        }
        __syncthreads();
    }

#pragma unroll
    for (int mi = 0; mi < 4; mi++) {
        int r0 = rowBase + wm * 64 + mi * 16 + l4;
#pragma unroll
        for (int ni = 0; ni < 4; ni++) {
            int cc = colBase + wn * 32 + ni * 8 + l3 * 2;
            float* cr = c[mi * 4 + ni];
            if (r0 < N)
                *(float2*)(C + (size_t)r0 * M + cc) = make_float2(cr[0], cr[1]);
            if (r0 + 8 < N)
                *(float2*)(C + (size_t)(r0 + 8) * M + cc) = make_float2(cr[2], cr[3]);
        }
    }
}

// ---------------- layer-1: 1 warp per node, 4-edge unrolled -----------------
// Per edge: lane holds float4 pair {lane, 32+lane}; head logits reduced over
// 8-lane groups (two heads per lane), matching R13 exactly.
__device__ __forceinline__ void edge1_logit(
        const float4& a0, const float4& a1, const float4& b0, const float4& b1,
        const float4& t0, const float4& t1, float& p0, float& p1) {
    float v;
    p0 = 0.f; p1 = 0.f;
    v = a0.x + b0.x; p0 += (v > 0.f ? v : 0.2f * v) * t0.x;
    v = a0.y + b0.y; p0 += (v > 0.f ? v : 0.2f * v) * t0.y;
    v = a0.z + b0.z; p0 += (v > 0.f ? v : 0.2f * v) * t0.z;
    v = a0.w + b0.w; p0 += (v > 0.f ? v : 0.2f * v) * t0.w;
    v = a1.x + b1.x; p1 += (v > 0.f ? v : 0.2f * v) * t1.x;
    v = a1.y + b1.y; p1 += (v > 0.f ? v : 0.2f * v) * t1.y;
    v = a1.z + b1.z; p1 += (v > 0.f ? v : 0.2f * v) * t1.z;
    v = a1.w + b1.w; p1 += (v > 0.f ? v : 0.2f * v) * t1.w;
}

__global__ void agg_node1(const float* __restrict__ att,
                          const float* __restrict__ b1) {
    int n = (int)((blockIdx.x * blockDim.x + threadIdx.x) >> 5);
    int lane = threadIdx.x & 31;
    if (n >= NN) return;

    int end = g_pos[n];
    int start = end - g_cnt[n];

    const float4* pa = (const float4*)att;
    float4 t0 = pa[lane], t1 = pa[32 + lane];

    const float4* pr = (const float4*)(g_xlr1 + (size_t)n * 512 + 256);
    float4 b0 = pr[lane], b1v = pr[32 + lane];

    float4 acc0 = make_float4(0, 0, 0, 0), acc1 = make_float4(0, 0, 0, 0);
    float dn0 = 0.f, dn1 = 0.f;

    int e = start;
    for (; e + 3 < end; e += 4) {
        int s0 = g_perm[e],     s1 = g_perm[e + 1];
        int s2 = g_perm[e + 2], s3 = g_perm[e + 3];
        const float4* p0p = (const float4*)(g_xlr1 + (size_t)s0 * 512);
        const float4* p1p = (const float4*)(g_xlr1 + (size_t)s1 * 512);
        const float4* p2p = (const float4*)(g_xlr1 + (size_t)s2 * 512);
        const float4* p3p = (const float4*)(g_xlr1 + (size_t)s3 * 512);
        float4 x00 = p0p[lane], x01 = p0p[32 + lane];
        float4 x10 = p1p[lane], x11 = p1p[32 + lane];
        float4 x20 = p2p[lane], x21 = p2p[32 + lane];
        float4 x30 = p3p[lane], x31 = p3p[32 + lane];

        float pA0, pA1, pB0, pB1, pC0, pC1, pD0, pD1;
        edge1_logit(x00, x01, b0, b1v, t0, t1, pA0, pA1);
        edge1_logit(x10, x11, b0, b1v, t0, t1, pB0, pB1);
        edge1_logit(x20, x21, b0, b1v, t0, t1, pC0, pC1);
        edge1_logit(x30, x31, b0, b1v, t0, t1, pD0, pD1);

#pragma unroll
        for (int o = 1; o < 8; o <<= 1) {
            pA0 += __shfl_xor_sync(0xFFFFFFFFu, pA0, o);
            pA1 += __shfl_xor_sync(0xFFFFFFFFu, pA1, o);
            pB0 += __shfl_xor_sync(0xFFFFFFFFu, pB0, o);
            pB1 += __shfl_xor_sync(0xFFFFFFFFu, pB1, o);
            pC0 += __shfl_xor_sync(0xFFFFFFFFu, pC0, o);
            pC1 += __shfl_xor_sync(0xFFFFFFFFu, pC1, o);
            pD0 += __shfl_xor_sync(0xFFFFFFFFu, pD0, o);
            pD1 += __shfl_xor_sync(0xFFFFFFFFu, pD1, o);
        }
        float eA0 = __expf(pA0), eA1 = __expf(pA1);
        float eB0 = __expf(pB0), eB1 = __expf(pB1);
        float eC0 = __expf(pC0), eC1 = __expf(pC1);
        float eD0 = __expf(pD0), eD1 = __expf(pD1);

        acc0.x += x00.x * eA0 + x10.x * eB0 + x20.x * eC0 + x30.x * eD0;
        acc0.y += x00.y * eA0 + x10.y * eB0 + x20.y * eC0 + x30.y * eD0;
        acc0.z += x00.z * eA0 + x10.z * eB0 + x20.z * eC0 + x30.z * eD0;
        acc0.w += x00.w * eA0 + x10.w * eB0 + x20.w * eC0 + x30.w * eD0;
        acc1.x += x01.x * eA1 + x11.x * eB1 + x21.x * eC1 + x31.x * eD1;
        acc1.y += x01.y * eA1 + x11.y * eB1 + x21.y * eC1 + x31.y * eD1;
        acc1.z += x01.z * eA1 + x11.z * eB1 + x21.z * eC1 + x31.z * eD1;
        acc1.w += x01.w * eA1 + x11.w * eB1 + x21.w * eC1 + x31.w * eD1;
        dn0 += eA0 + eB0 + eC0 + eD0;
        dn1 += eA1 + eB1 + eC1 + eD1;
    }
    for (; e < end; e++) {
        int s = g_perm[e];
        const float4* pl = (const float4*)(g_xlr1 + (size_t)s * 512);
        float4 a0 = pl[lane], a1 = pl[32 + lane];
        float p0, p1;
        edge1_logit(a0, a1, b0, b1v, t0, t1, p0, p1);
#pragma unroll
        for (int o = 1; o < 8; o <<= 1) {
            p0 += __shfl_xor_sync(0xFFFFFFFFu, p0, o);
            p1 += __shfl_xor_sync(0xFFFFFFFFu, p1, o);
        }
        float e0 = __expf(p0), e1 = __expf(p1);
        acc0.x += a0.x * e0; acc0.y += a0.y * e0; acc0.z += a0.z * e0; acc0.w += a0.w * e0;
        acc1.x += a1.x * e1; acc1.y += a1.y * e1; acc1.z += a1.z * e1; acc1.w += a1.w * e1;
        dn0 += e0; dn1 += e1;
    }

    float inv0 = 1.f / (dn0 + 1e-16f);
    float inv1 = 1.f / (dn1 + 1e-16f);
    const float4* pb = (const float4*)b1;
    float4 bb0 = pb[lane], bb1 = pb[32 + lane];
    float4 r0, r1;
    r0.x = fmaxf(acc0.x * inv0 + bb0.x, 0.f);
    r0.y = fmaxf(acc0.y * inv0 + bb0.y, 0.f);
    r0.z = fmaxf(acc0.z * inv0 + bb0.z, 0.f);
    r0.w = fmaxf(acc0.w * inv0 + bb0.w, 0.f);
    r1.x = fmaxf(acc1.x * inv1 + bb1.x, 0.f);
    r1.y = fmaxf(acc1.y * inv1 + bb1.y, 0.f);
    r1.z = fmaxf(acc1.z * inv1 + bb1.z, 0.f);
    r1.w = fmaxf(acc1.w * inv1 + bb1.w, 0.f);
    float4* ph = (float4*)(g_h1 + (size_t)n * F1);
    ph[lane] = r0;
    ph[32 + lane] = r1;
}

// ---------------- layer-2: half-warp per node, 4-edge unrolled --------------
__global__ void agg_node2(const float* __restrict__ att,
                          const float* __restrict__ b2,
                          float* __restrict__ out) {
    int n = (int)((blockIdx.x * blockDim.x + threadIdx.x) >> 4);
    int l16 = threadIdx.x & 15;
    unsigned hm = 0xFFFFu << (threadIdx.x & 16);
    if (n >= NN) return;

    int end = g_pos[n];
    int start = end - g_cnt[n];

    float4 t = ((const float4*)att)[l16];
    float4 b = ((const float4*)(g_xlr2 + (size_t)n * 128 + 64))[l16];

    float4 acc = make_float4(0, 0, 0, 0);
    float dn = 0.f;

    int e = start;
    for (; e + 3 < end; e += 4) {
        int s0 = g_perm[e], s1 = g_perm[e + 1], s2 = g_perm[e + 2], s3 = g_perm[e + 3];
        float4 a0 = ((const float4*)(g_xlr2 + (size_t)s0 * 128))[l16];
        float4 a1 = ((const float4*)(g_xlr2 + (size_t)s1 * 128))[l16];
        float4 a2 = ((const float4*)(g_xlr2 + (size_t)s2 * 128))[l16];
        float4 a3 = ((const float4*)(g_xlr2 + (size_t)s3 * 128))[l16];

        float v, p0 = 0.f, p1 = 0.f, p2 = 0.f, p3 = 0.f;
        v = a0.x + b.x; p0 += (v > 0.f ? v : 0.2f * v) * t.x;
        v = a0.y + b.y; p0 += (v > 0.f ? v : 0.2f * v) * t.y;
        v = a0.z + b.z; p0 += (v > 0.f ? v : 0.2f * v) * t.z;
        v = a0.w + b.w; p0 += (v > 0.f ? v : 0.2f * v) * t.w;
        v = a1.x + b.x; p1 += (v > 0.f ? v : 0.2f * v) * t.x;
        v = a1.y + b.y; p1 += (v > 0.f ? v : 0.2f * v) * t.y;
        v = a1.z + b.z; p1 += (v > 0.f ? v : 0.2f * v) * t.z;
        v = a1.w + b.w; p1 += (v > 0.f ? v : 0.2f * v) * t.w;
        v = a2.x + b.x; p2 += (v > 0.f ? v : 0.2f * v) * t.x;
        v = a2.y + b.y; p2 += (v > 0.f ? v : 0.2f * v) * t.y;
        v = a2.z + b.z; p2 += (v > 0.f ? v : 0.2f * v) * t.z;
        v = a2.w + b.w; p2 += (v > 0.f ? v : 0.2f * v) * t.w;
        v = a3.x + b.x; p3 += (v > 0.f ? v : 0.2f * v) * t.x;
        v = a3.y + b.y; p3 += (v > 0.f ? v : 0.2f * v) * t.y;
        v = a3.z + b.z; p3 += (v > 0.f ? v : 0.2f * v) * t.z;
        v = a3.w + b.w; p3 += (v > 0.f ? v : 0.2f * v) * t.w;

#pragma unroll
        for (int o = 1; o < 16; o <<= 1) {
            p0 += __shfl_xor_sync(hm, p0, o);
            p1 += __shfl_xor_sync(hm, p1, o);
            p2 += __shfl_xor_sync(hm, p2, o);
            p3 += __shfl_xor_sync(hm, p3, o);
        }
        float e0 = __expf(p0), e1 = __expf(p1), e2 = __expf(p2), e3 = __expf(p3);

        acc.x += a0.x * e0 + a1.x * e1 + a2.x * e2 + a3.x * e3;
        acc.y += a0.y * e0 + a1.y * e1 + a2.y * e2 + a3.y * e3;
        acc.z += a0.z * e0 + a1.z * e1 + a2.z * e2 + a3.z * e3;
        acc.w += a0.w * e0 + a1.w * e1 + a2.w * e2 + a3.w * e3;
        dn += e0 + e1 + e2 + e3;
    }
    for (; e < end; e++) {
        int s = g_perm[e];
        float4 a = ((const float4*)(g_xlr2 + (size_t)s * 128))[l16];
        float v, p = 0.f;
        v = a.x + b.x; p += (v > 0.f ? v : 0.2f * v) * t.x;
        v = a.y + b.y; p += (v > 0.f ? v : 0.2f * v) * t.y;
        v = a.z + b.z; p += (v > 0.f ? v : 0.2f * v) * t.z;
        v = a.w + b.w; p += (v > 0.f ? v : 0.2f * v) * t.w;
#pragma unroll
        for (int o = 1; o < 16; o <<= 1) p += __shfl_xor_sync(hm, p, o);
        float ex = __expf(p);
        acc.x += a.x * ex; acc.y += a.y * ex; acc.z += a.z * ex; acc.w += a.w * ex;
        dn += ex;
    }

    float inv = 1.f / (dn + 1e-16f);
    float4 bb = ((const float4*)b2)[l16];
    float4 vv;
    vv.x = acc.x * inv + bb.x;
    vv.y = acc.y * inv + bb.y;
    vv.z = acc.z * inv + bb.z;
    vv.w = acc.w * inv + bb.w;

    float mx = fmaxf(fmaxf(vv.x, vv.y), fmaxf(vv.z, vv.w));
#pragma unroll
    for (int o = 1; o < 16; o <<= 1) mx = fmaxf(mx, __shfl_xor_sync(hm, mx, o));
    float se = __expf(vv.x - mx) + __expf(vv.y - mx) + __expf(vv.z - mx) + __expf(vv.w - mx);
#pragma unroll
    for (int o = 1; o < 16; o <<= 1) se += __shfl_xor_sync(hm, se, o);
    float lse = mx + __logf(se);

    ((float4*)(out + (size_t)n * F2))[l16] = vv;
    float4 ls;
    ls.x = vv.x - lse; ls.y = vv.y - lse; ls.z = vv.z - lse; ls.w = vv.w - lse;
    ((float4*)(out + (size_t)NN * F2 + (size_t)n * F2))[l16] = ls;
}

// ---------------- launch ----------------------------------------------------
extern "C" void kernel_launch(void* const* d_in, const int* in_sizes, int n_in,
                              void* d_out, int out_size) {
    const float* x    = (const float*)d_in[0];
    const int*   ei   = (const int*)d_in[1];     // JAX canonicalizes int64 -> int32
    const float* Wl1  = (const float*)d_in[2];
    const float* Wr1  = (const float*)d_in[3];
    const float* att1 = (const float*)d_in[4];
    const float* b1   = (const float*)d_in[5];
    const float* Wl2  = (const float*)d_in[6];
    const float* Wr2  = (const float*)d_in[7];
    const float* att2 = (const float*)d_in[8];
    const float* b2   = (const float*)d_in[9];
    float* out = (float*)d_out;

    int E = in_sizes[1] / 2;
    if (E > EE) E = EE;
    int N = in_sizes[0] / F1;
    if (N > NN) N = NN;

    void *xlr1p, *xlr2p, *h1p, *bp1p, *bp2p;
    cudaGetSymbolAddress(&xlr1p, g_xlr1);
    cudaGetSymbolAddress(&xlr2p, g_xlr2);
    cudaGetSymbolAddress(&h1p,  g_h1);
    cudaGetSymbolAddress(&bp1p, g_Bp1);
    cudaGetSymbolAddress(&bp2p, g_Bp2);

    static cudaStream_t sA = nullptr, sB = nullptr;
    static cudaEvent_t ev0 = nullptr, evS = nullptr, evG = nullptr;
    if (!sA) {
        cudaStreamCreateWithFlags(&sA, cudaStreamNonBlocking);
        cudaStreamCreateWithFlags(&sB, cudaStreamNonBlocking);
        cudaEventCreateWithFlags(&ev0, cudaEventDisableTiming);
        cudaEventCreateWithFlags(&evS, cudaEventDisableTiming);
        cudaEventCreateWithFlags(&evG, cudaEventDisableTiming);
    }

    // fork
    cudaEventRecord(ev0, 0);
    cudaStreamWaitEvent(sA, ev0, 0);
    cudaStreamWaitEvent(sB, ev0, 0);

    // stream A: CSR build (counting sort by dst)
    init_kernel<<<(NN + 255) / 256, 256, 0, sA>>>();
    hist_kernel<<<1024, 256, 0, sA>>>(ei, E);
    scanA_kernel<<<SCAN_B, 256, 0, sA>>>();
    scanB_kernel<<<1, 256, 0, sA>>>();
    scanC_kernel<<<SCAN_B, 256, 0, sA>>>();
    scatter_kernel<<<1024, 256, 0, sA>>>(ei, E);
    cudaEventRecord(evS, sA);

    // stream B: weight packing + layer-1 projection [N,256]@[256,512]
    pack_kernel<<<(256 * 256 + 255) / 256, 256, 0, sB>>>(Wl1, Wr1, (float*)bp1p, 256, 256);
    pack_kernel<<<(256 * 64 + 255) / 256, 256, 0, sB>>>(Wl2, Wr2, (float*)bp2p, 256, 64);
    dim3 grid1(512 / 128, (N + 127) / 128);
    tf32_gemm<<<grid1, 256, 0, sB>>>(x, (const float*)bp1p, (float*)xlr1p, N, F1, 512);
    cudaEventRecord(evG, sB);

    // join
    cudaStreamWaitEvent(0, evS, 0);
    cudaStreamWaitEvent(0, evG, 0);

    // layer-1 aggregation: 1 warp per node, 4-edge unrolled
    agg_node1<<<(NN + 7) / 8, 256>>>(att1, b1);

    // layer-2 projection: [N,256]@[256,128] on h1 -> xlr2
    dim3 grid2(1, (N + 127) / 128);
    tf32_gemm<<<grid2, 256>>>((const float*)h1p, (const float*)bp2p, (float*)xlr2p, N, F1, 128);

    // layer-2 aggregation + bias + log_softmax -> out
    agg_node2<<<(NN + 15) / 16, 256>>>(att2, b2, out);

    (void)n_in; (void)out_size;
}